// round 16
// baseline (speedup 1.0000x reference)
#include <cuda_runtime.h>
#include <math.h>
#include <float.h>

// Problem dims
#define LL 64
#define BB 128
#define EE 512
#define HH 256
#define H4 1024
#define DD 512      // 2H
#define NG 2048     // fused gate dim (both directions)
#define NROWS 16384 // 2 sentences * L * B

typedef unsigned long long ull;

// f32x2 packed helpers
#define FMA2(d, a, b) asm("fma.rn.f32x2 %0, %1, %2, %0;" : "+l"(d) : "l"(a), "l"(b))
#define PACK2(d, lo, hi) asm("mov.b64 %0, {%1, %2};" : "=l"(d) : "f"(lo), "f"(hi))
#define DUP2(d, x) asm("mov.b64 %0, {%1, %1};" : "=l"(d) : "f"(x))
#define UNPACK2(lo, hi, v) asm("mov.b64 {%0, %1}, %2;" : "=f"(lo), "=f"(hi) : "l"(v))

// cp.async (LDGSTS) helpers: .cg = L2-only (required for cross-SM h coherence)
#define CP_ASYNC16(smem_u32, gptr) \
    asm volatile("cp.async.cg.shared.global [%0], [%1], 16;" :: "r"(smem_u32), "l"(gptr) : "memory")
#define CP_COMMIT() asm volatile("cp.async.commit_group;" ::: "memory")
#define CP_WAIT(n)  asm volatile("cp.async.wait_group %0;" :: "n"(n) : "memory")

__device__ __forceinline__ float tanh_fast(float x) {
    float y;
    asm("tanh.approx.f32 %0, %1;" : "=f"(y) : "f"(x));
    return y;
}
__device__ __forceinline__ float sig_fast(float x) {
    return fmaf(0.5f, tanh_fast(0.5f * x), 0.5f);
}

// ---------------- scratch (device globals; no allocation allowed) ----------
__device__ float g_x[2 * LL * BB * EE];          // embedded inputs  (33.5 MB)
__device__ float g_xg[(size_t)2 * LL * BB * NG]; // input-gate GEMM out (134 MB)
__device__ float g_o[2 * LL * BB * DD];          // o1, o2 outputs (L,B,D) (33.5 MB)
__device__ float g_h[2 * 4 * BB * HH];           // double-buffered h state (1 MB)
__device__ float g_mp1[BB * DD];
__device__ float g_attsm[BB * LL];
__device__ unsigned g_syncs[4 * 32];             // per-scan barrier counters
__device__ unsigned g_dones[4 * 32];             // per-scan reset counters

// ---------------- kernel 0: zero h state ----------------
__global__ void zero_h_kernel() {
    int i = blockIdx.x * blockDim.x + threadIdx.x;
    if (i < 2 * 4 * BB * HH) g_h[i] = 0.0f;
}

// ---------------- kernel 1: embedding gather ----------------
__global__ void gather_kernel(const int* __restrict__ t1, const int* __restrict__ t2,
                              const float* __restrict__ emb) {
    int row = blockIdx.x;            // 0..16383
    int s   = row >> 13;
    int r   = row & 8191;
    int tok = s ? t2[r] : t1[r];
    const float4* src = (const float4*)(emb + (size_t)tok * EE);
    float4* dst = (float4*)(g_x + (size_t)row * EE);
    int tid = threadIdx.x;           // 128 threads, 128 float4 per row
    dst[tid] = src[tid];
}

// ---------------- kernel 2: input projection GEMM (k-packed, zero DUPs) ----
// C[row][n] = sum_k A[row][k]*W[n][k] + bias[n]
// BM=128, BN=64, BK=32; 256 threads; 8x4 thread tile; acc packed along K.
// Tiles stored [row][k] (k contiguous) -> loads are straight copies and both
// FMA2 operands come packed directly out of LDS.128. 2 CTAs/SM.
#define GASTR 36   // tile row stride (floats): 144B % 128B = 16 -> broadcast-friendly

__global__ __launch_bounds__(256, 2) void gemm_kernel(
    const float* __restrict__ Wf, const float* __restrict__ Wb,
    const float* __restrict__ bihf, const float* __restrict__ bhhf,
    const float* __restrict__ bihb, const float* __restrict__ bhhb) {
    __shared__ float As[128 * GASTR];   // 18.4 KB
    __shared__ float Bs[64 * GASTR];    //  9.2 KB

    int bm = blockIdx.x;             // 0..127  (M tiles of 128)
    int bn = blockIdx.y;             // 0..31   (N tiles of 64)
    int n0 = bn * 64;
    int dirb = (n0 >= 1024) ? 1 : 0;
    const float* W = dirb ? Wb : Wf;
    int nW0 = dirb ? (n0 - 1024) : n0;

    const float* A = g_x + (size_t)bm * 128 * EE;
    int tid = threadIdx.x;
    int tr = tid >> 4;               // 0..15 -> rows r0..r0+7
    int tc = tid & 15;               // 0..15 -> cols c0..c0+3
    int r0 = tr * 8, c0 = tc * 4;

    ull acc2[8][4];
#pragma unroll
    for (int i = 0; i < 8; i++)
#pragma unroll
        for (int j = 0; j < 4; j++) acc2[i][j] = 0ULL;

    for (int k0 = 0; k0 < EE; k0 += 32) {
        // A tile: 128 rows x 32 floats, straight copy (k contiguous)
#pragma unroll
        for (int i = 0; i < 4; i++) {
            int idx = tid + 256 * i;         // 1024 float4
            int row = idx >> 3, k4 = idx & 7;
            *(float4*)&As[row * GASTR + k4 * 4] =
                *(const float4*)(A + (size_t)row * EE + k0 + k4 * 4);
        }
        // B tile: 64 rows x 32 floats
#pragma unroll
        for (int i = 0; i < 2; i++) {
            int idx = tid + 256 * i;         // 512 float4
            int row = idx >> 3, k4 = idx & 7;
            *(float4*)&Bs[row * GASTR + k4 * 4] =
                *(const float4*)(W + (size_t)(nW0 + row) * EE + k0 + k4 * 4);
        }
        __syncthreads();

#pragma unroll
        for (int k4 = 0; k4 < 8; k4++) {
            ulonglong2 av[8], bv[4];
#pragma unroll
            for (int i = 0; i < 8; i++)
                av[i] = *(const ulonglong2*)&As[(r0 + i) * GASTR + k4 * 4];
#pragma unroll
            for (int j = 0; j < 4; j++)
                bv[j] = *(const ulonglong2*)&Bs[(c0 + j) * GASTR + k4 * 4];
#pragma unroll
            for (int i = 0; i < 8; i++)
#pragma unroll
                for (int j = 0; j < 4; j++) {
                    FMA2(acc2[i][j], av[i].x, bv[j].x);
                    FMA2(acc2[i][j], av[i].y, bv[j].y);
                }
        }
        __syncthreads();
    }

    // fold even/odd partials + bias, store (4 consecutive cols -> float4)
    float bs[4];
#pragma unroll
    for (int j = 0; j < 4; j++) {
        int n = n0 + c0 + j;
        bs[j] = dirb ? (bihb[n - 1024] + bhhb[n - 1024]) : (bihf[n] + bhhf[n]);
    }
#pragma unroll
    for (int i = 0; i < 8; i++) {
        float v[4];
#pragma unroll
        for (int j = 0; j < 4; j++) {
            float lo, hi;
            UNPACK2(lo, hi, acc2[i][j]);
            v[j] = lo + hi + bs[j];
        }
        *(float4*)(g_xg + (size_t)(bm * 128 + r0 + i) * NG + n0 + c0) =
            make_float4(v[0], v[1], v[2], v[3]);
    }
}

// ---------------- kernel 3: persistent LSTM recurrence (R11 measured-best) --
// K-PACKED f32x2 accumulators. 128 blocks = 4 scans x 32 slices; 256 threads.
// Thread (ct = tid&7 unit, bt = tid>>3 0..31): 4 batches (bt + 32*bi), 4 gates.
// acc2[bi][g] = (even-k, odd-k) partial sums; zero DUP/PACK in inner loop.
#define WST 1028                     // sh_w unit stride: 4112B % 128B = 16 -> conflict-free
#define HST 260                      // sh_h batch stride: 1040B % 128B = 16 -> conflict-free

__global__ __launch_bounds__(256, 1) void lstm_kernel(const float* __restrict__ Whh_f,
                                                      const float* __restrict__ Whh_b) {
    extern __shared__ float sm[];
    float* sh_w = sm;                     // [8 units][1028] : g*256 + k (k contiguous)
    float* sh_h = sm + 8 * WST;           // [128 batches][260] : k contiguous

    const int tid = threadIdx.x;
    const int rec = blockIdx.x >> 5;      // (s1,f)(s1,b)(s2,f)(s2,b)
    const int slice = blockIdx.x & 31;
    const int s = rec >> 1;
    const int dir = rec & 1;
    const int ct = tid & 7;               // unit within slice
    const int bt = tid >> 3;              // 0..31
    const int j = slice * 8 + ct;         // hidden unit 0..255
    const float* Whh = dir ? Whh_b : Whh_f;
    const unsigned shh_u32 = (unsigned)__cvta_generic_to_shared(sh_h);
    unsigned* syncp = &g_syncs[rec * 32];
    unsigned* donep = &g_dones[rec * 32];

    // Build weights: sh_w[jj*WST + g*256 + k] = Whh[g*256 + slice*8 + jj][k]
    for (int idx = tid; idx < 8 * 4 * 64; idx += 256) {
        int jj = idx >> 8;                // 0..7
        int g  = (idx >> 6) & 3;
        int k4 = idx & 63;
        float4 v = *(const float4*)(Whh + (size_t)(g * 256 + slice * 8 + jj) * HH + k4 * 4);
        *(float4*)(sh_w + jj * WST + g * 256 + k4 * 4) = v;
    }

    const float* wbase = sh_w + ct * WST;
    float c_st[4] = {0.f, 0.f, 0.f, 0.f};

    for (int t = 0; t < 64; ++t) {
        const int l = dir ? (63 - t) : t;

        // stage h_prev via cp.async.cg in two chunks (k 0..127 / 128..255)
        const float* hsrc = g_h + (size_t)((t & 1) * 4 + rec) * BB * HH;
#pragma unroll 4
        for (int it = 0; it < 16; it++) {           // chunk0: k4 0..31
            int idx = tid + 256 * it;               // 4096 float4
            int b = idx >> 5, k4 = idx & 31;
            CP_ASYNC16(shh_u32 + (unsigned)(b * HST + k4 * 4) * 4u,
                       hsrc + (size_t)b * HH + k4 * 4);
        }
        CP_COMMIT();
#pragma unroll 4
        for (int it = 0; it < 16; it++) {           // chunk1: k4 32..63
            int idx = tid + 256 * it;
            int b = idx >> 5, k4 = 32 + (idx & 31);
            CP_ASYNC16(shh_u32 + (unsigned)(b * HST + k4 * 4) * 4u,
                       hsrc + (size_t)b * HH + k4 * 4);
        }
        CP_COMMIT();

        // xg prefetch (independent LDGs, overlap with cp.async)
        const float* xgp = g_xg + ((size_t)(s * 8192 + l * 128)) * NG + dir * 1024 + j;
        float xv0[4], xv1[4], xv2[4], xv3[4];
#pragma unroll
        for (int g = 0; g < 4; g++) {
            xv0[g] = __ldcg(xgp + (size_t)bt * NG + g * 256);
            xv1[g] = __ldcg(xgp + (size_t)(bt + 32) * NG + g * 256);
            xv2[g] = __ldcg(xgp + (size_t)(bt + 64) * NG + g * 256);
            xv3[g] = __ldcg(xgp + (size_t)(bt + 96) * NG + g * 256);
        }

        // k-packed accumulators: acc2[bi][g] = (sum over even k, sum over odd k)
        ull acc2[4][4];
#pragma unroll
        for (int bi = 0; bi < 4; bi++)
#pragma unroll
            for (int g = 0; g < 4; g++) acc2[bi][g] = 0ULL;

        CP_WAIT(1);          // chunk0 landed
        __syncthreads();

        // first half (k4 0..31) while chunk1 streams
#pragma unroll 4
        for (int k4 = 0; k4 < 32; ++k4) {
            ulonglong2 hp[4], wp[4];
#pragma unroll
            for (int bi = 0; bi < 4; bi++)
                hp[bi] = *(const ulonglong2*)(sh_h + (bt + 32 * bi) * HST + k4 * 4);
#pragma unroll
            for (int g = 0; g < 4; g++)
                wp[g] = *(const ulonglong2*)(wbase + g * 256 + k4 * 4);
#pragma unroll
            for (int bi = 0; bi < 4; bi++)
#pragma unroll
                for (int g = 0; g < 4; g++) {
                    FMA2(acc2[bi][g], hp[bi].x, wp[g].x);
                    FMA2(acc2[bi][g], hp[bi].y, wp[g].y);
                }
        }

        CP_WAIT(0);          // chunk1 landed
        __syncthreads();

        // second half (k4 32..63)
#pragma unroll 4
        for (int k4 = 32; k4 < 64; ++k4) {
            ulonglong2 hp[4], wp[4];
#pragma unroll
            for (int bi = 0; bi < 4; bi++)
                hp[bi] = *(const ulonglong2*)(sh_h + (bt + 32 * bi) * HST + k4 * 4);
#pragma unroll
            for (int g = 0; g < 4; g++)
                wp[g] = *(const ulonglong2*)(wbase + g * 256 + k4 * 4);
#pragma unroll
            for (int bi = 0; bi < 4; bi++)
#pragma unroll
                for (int g = 0; g < 4; g++) {
                    FMA2(acc2[bi][g], hp[bi].x, wp[g].x);
                    FMA2(acc2[bi][g], hp[bi].y, wp[g].y);
                }
        }

        // fold even/odd sums + xg, nonlinearity, state update, writes
        float* hdst = g_h + (size_t)(((t + 1) & 1) * 4 + rec) * BB * HH;
        float* odst = g_o + (size_t)s * LL * BB * DD + (size_t)l * BB * DD + dir * HH + j;
#pragma unroll
        for (int bi = 0; bi < 4; bi++) {
            int b = bt + 32 * bi;
            const float* xv = (bi == 0) ? xv0 : (bi == 1) ? xv1 : (bi == 2) ? xv2 : xv3;
            float gate[4];
#pragma unroll
            for (int g = 0; g < 4; g++) {
                float lo, hi;
                UNPACK2(lo, hi, acc2[bi][g]);
                gate[g] = xv[g] + lo + hi;
            }
            float ig = sig_fast(gate[0]);
            float fg = sig_fast(gate[1]);
            float gg = tanh_fast(gate[2]);
            float og = sig_fast(gate[3]);
            float c = fmaf(fg, c_st[bi], ig * gg);
            c_st[bi] = c;
            float h = og * tanh_fast(c);
            hdst[(size_t)b * HH + j] = h;
            odst[(size_t)b * DD] = h;
        }

        // per-scan barrier (32 blocks of this scan, all co-resident)
        __syncthreads();   // all threads' stores issued before arrival
        if (tid == 0) {
            __threadfence();
            atomicAdd(syncp, 1u);
            unsigned target = 32u * (unsigned)(t + 1);
            while (*((volatile unsigned*)syncp) < target) { }
            __threadfence();
        }
        __syncthreads();
    }

    // self-reset for graph replays (per scan)
    if (tid == 0) {
        unsigned old = atomicAdd(donep, 1u);
        if (old == 31u) {
            *donep = 0u;
            *syncp = 0u;
            __threadfence();
        }
    }
}

// ---------------- kernel 4: mp1 = max over time of o1 ----------------
__global__ void mp1_kernel() {
    int b = blockIdx.x;
    for (int d = threadIdx.x; d < DD; d += blockDim.x) {
        float m = -FLT_MAX;
#pragma unroll 8
        for (int l = 0; l < LL; l++)
            m = fmaxf(m, g_o[(size_t)l * BB * DD + b * DD + d]);
        g_mp1[b * DD + d] = m;
    }
}

// ---------------- kernel 5: attention + softmax (raw-reshape semantics) ----
// 256 threads: l = tid&63, d-part = tid>>6 (4 partials of 128 d each)
__global__ void att_kernel() {
    __shared__ float smp[DD];
    __shared__ float spart[4][LL];
    __shared__ float sat[LL];
    int b = blockIdx.x, tid = threadIdx.x;
    int l = tid & 63, part = tid >> 6;
    const float* o2 = g_o + (size_t)LL * BB * DD;
    for (int d = tid; d < DD; d += 256) smp[d] = g_mp1[b * DD + d];
    __syncthreads();
    float a = 0.0f;
    const float* o2b = o2 + (size_t)b * DD * LL + l;
    for (int d = part * 128; d < part * 128 + 128; d++)
        a = fmaf(smp[d], o2b[(size_t)d * LL], a);
    spart[part][l] = a;
    __syncthreads();
    if (tid < LL) {
        float at = spart[0][tid] + spart[1][tid] + spart[2][tid] + spart[3][tid];
        sat[tid] = at;
    }
    __syncthreads();
    if (tid < LL) {
        float mx = -FLT_MAX;
        for (int i = 0; i < LL; i++) mx = fmaxf(mx, sat[i]);
        float ssum = 0.0f;
        for (int i = 0; i < LL; i++) ssum += expf(sat[i] - mx);
        g_attsm[b * LL + tid] = expf(sat[tid] - mx) / ssum;
    }
}

// ---------------- kernel 6: new_pool + sim (fused) ----------------
__global__ void sim_kernel(float* __restrict__ out) {
    __shared__ float sal[LL];
    __shared__ float red[256];
    int b = blockIdx.x, tid = threadIdx.x;
    if (tid < LL) sal[tid] = g_attsm[b * LL + tid];
    __syncthreads();
    const float* o2 = g_o + (size_t)LL * BB * DD;
    float local = 0.0f;
    for (int d = tid; d < DD; d += 256) {
        float np = 0.0f;
#pragma unroll 8
        for (int l = 0; l < LL; l++)
            np = fmaf(sal[l], o2[(size_t)b * LL * DD + l * DD + d], np);
        local += fabsf(g_mp1[b * DD + d] - np);
    }
    red[tid] = local;
    __syncthreads();
    for (int s2 = 128; s2 > 0; s2 >>= 1) {
        if (tid < s2) red[tid] += red[tid + s2];
        __syncthreads();
    }
    if (tid == 0) out[b] = expf(-red[0]);
}

// ---------------- kernel 7: commonWords + e1h/e2h ----------------
__global__ void e_kernel(const int* __restrict__ t1, const int* __restrict__ t2,
                         float* __restrict__ out) {
    __shared__ int s1[LL];
    __shared__ int spos[LL];
    __shared__ int smask[LL];
    __shared__ int shas;
    int b = blockIdx.x, tid = threadIdx.x;
    if (tid == 0) shas = 0;
    if (tid < LL) s1[tid] = t1[tid * BB + b];
    __syncthreads();
    if (tid < LL) {
        int tok2 = t2[tid * BB + b];
        int d = -1;
        for (int jj = 0; jj < LL; jj++)
            if (s1[jj] == tok2) d = jj;
        int m = (d > 1) && (tok2 > 0);
        smask[tid] = m;
        spos[tid] = min(max(d, 0), LL - 1);
        if (m) atomicOr(&shas, 1);
    }
    __syncthreads();
    int has = shas;
    const float* o1 = g_o;
    const float* o2 = g_o + (size_t)LL * BB * DD;
    for (int d = tid; d < DD; d += 256) {
        float m1 = -FLT_MAX, m2 = -FLT_MAX;
        for (int i = 0; i < LL; i++) {
            if (smask[i]) {
                m1 = fmaxf(m1, o1[(size_t)spos[i] * BB * DD + b * DD + d]);
                m2 = fmaxf(m2, o2[(size_t)i * BB * DD + b * DD + d]);
            }
        }
        out[128 + b * DD + d] = has ? m1 : 0.0f;
        out[128 + BB * DD + b * DD + d] = has ? m2 : 0.0f;
    }
}

// ---------------- launch ----------------
extern "C" void kernel_launch(void* const* d_in, const int* in_sizes, int n_in,
                              void* d_out, int out_size) {
    const int* t1 = (const int*)d_in[0];
    const int* t2 = (const int*)d_in[1];
    const float* emb = (const float*)d_in[2];
    const float* Wihf = (const float*)d_in[3];
    const float* Whhf = (const float*)d_in[4];
    const float* bihf = (const float*)d_in[5];
    const float* bhhf = (const float*)d_in[6];
    const float* Wihb = (const float*)d_in[7];
    const float* Whhb = (const float*)d_in[8];
    const float* bihb = (const float*)d_in[9];
    const float* bhhb = (const float*)d_in[10];
    float* out = (float*)d_out;

    zero_h_kernel<<<(2 * 4 * BB * HH + 255) / 256, 256>>>();
    gather_kernel<<<NROWS, 128>>>(t1, t2, emb);

    dim3 ggrid(128, 32);
    gemm_kernel<<<ggrid, 256>>>(Wihf, Wihb, bihf, bhhf, bihb, bhhb);

    const int lstm_smem = (8 * WST + 128 * HST) * 4;  // 166,016 B
    cudaFuncSetAttribute(lstm_kernel, cudaFuncAttributeMaxDynamicSharedMemorySize, lstm_smem);
    lstm_kernel<<<128, 256, lstm_smem>>>(Whhf, Whhb);

    mp1_kernel<<<BB, 128>>>();
    att_kernel<<<BB, 256>>>();
    sim_kernel<<<BB, 256>>>(out);
    e_kernel<<<BB, 256>>>(t1, t2, out);
}

// round 17
// speedup vs baseline: 1.3644x; 1.3644x over previous
#include <cuda_runtime.h>
#include <math.h>
#include <float.h>

// Problem dims
#define LL 64
#define BB 128
#define EE 512
#define HH 256
#define H4 1024
#define DD 512      // 2H
#define NG 2048     // fused gate dim (both directions)
#define NROWS 16384 // 2 sentences * L * B

typedef unsigned long long ull;

// f32x2 packed helpers
#define FMA2(d, a, b) asm("fma.rn.f32x2 %0, %1, %2, %0;" : "+l"(d) : "l"(a), "l"(b))
#define PACK2(d, lo, hi) asm("mov.b64 %0, {%1, %2};" : "=l"(d) : "f"(lo), "f"(hi))
#define DUP2(d, x) asm("mov.b64 %0, {%1, %1};" : "=l"(d) : "f"(x))
#define UNPACK2(lo, hi, v) asm("mov.b64 {%0, %1}, %2;" : "=f"(lo), "=f"(hi) : "l"(v))

// cp.async (LDGSTS) helpers: .cg = L2-only (required for cross-SM h coherence)
#define CP_ASYNC16(smem_u32, gptr) \
    asm volatile("cp.async.cg.shared.global [%0], [%1], 16;" :: "r"(smem_u32), "l"(gptr) : "memory")
#define CP_COMMIT() asm volatile("cp.async.commit_group;" ::: "memory")
#define CP_WAIT(n)  asm volatile("cp.async.wait_group %0;" :: "n"(n) : "memory")

__device__ __forceinline__ float tanh_fast(float x) {
    float y;
    asm("tanh.approx.f32 %0, %1;" : "=f"(y) : "f"(x));
    return y;
}
__device__ __forceinline__ float sig_fast(float x) {
    return fmaf(0.5f, tanh_fast(0.5f * x), 0.5f);
}

// ---------------- scratch (device globals; no allocation allowed) ----------
__device__ float g_x[2 * LL * BB * EE];          // embedded inputs  (33.5 MB)
__device__ float g_xg[(size_t)2 * LL * BB * NG]; // input-gate GEMM out (134 MB)
__device__ float g_o[2 * LL * BB * DD];          // o1, o2 outputs (L,B,D) (33.5 MB)
__device__ float g_h[2 * 4 * BB * HH];           // double-buffered h state (1 MB)
__device__ float g_attsm_unused[BB * LL];        // kept for layout stability
__device__ unsigned g_syncs[4 * 32];             // per-scan barrier counters
__device__ unsigned g_dones[4 * 32];             // per-scan reset counters

// ---------------- kernel 1: embedding gather ----------------
__global__ void gather_kernel(const int* __restrict__ t1, const int* __restrict__ t2,
                              const float* __restrict__ emb) {
    int row = blockIdx.x;            // 0..16383
    int s   = row >> 13;
    int r   = row & 8191;
    int tok = s ? t2[r] : t1[r];
    const float4* src = (const float4*)(emb + (size_t)tok * EE);
    float4* dst = (float4*)(g_x + (size_t)row * EE);
    int tid = threadIdx.x;           // 128 threads, 128 float4 per row
    dst[tid] = src[tid];
}

// ---------------- kernel 2: input projection GEMM ----------------
// (f32x2 packed, BK=16, register-staged double-buffered smem pipeline
//  — the R10/R11 measured-best configuration)
#define GTILE (16 * 132)

__global__ __launch_bounds__(256) void gemm_kernel(
    const float* __restrict__ Wf, const float* __restrict__ Wb,
    const float* __restrict__ bihf, const float* __restrict__ bhhf,
    const float* __restrict__ bihb, const float* __restrict__ bhhb) {
    extern __shared__ float gsm[];
    float* As0 = gsm;                  // [2][16][132]
    float* Bs0 = gsm + 2 * GTILE;      // [2][16][132]

    int bm = blockIdx.x;             // 0..127  (M tiles)
    int bn = blockIdx.y;             // 0..15   (N tiles of 128)
    int n0 = bn * 128;
    int dirb = (n0 >= 1024) ? 1 : 0;
    const float* W = dirb ? Wb : Wf;
    int nW0 = dirb ? (n0 - 1024) : n0;

    const float* A = g_x + (size_t)bm * 128 * EE;
    int tid = threadIdx.x;
    int tr = tid >> 4;               // 0..15 -> rows r0..r0+7 (4 packed pairs)
    int tc = tid & 15;               // 0..15 -> cols c0..c0+7
    int r0 = tr * 8, c0 = tc * 8;

    const int ar0 = tid >> 2,         ak0 = tid & 3;
    const int ar1 = (tid + 256) >> 2, ak1 = tid & 3;

    ull acc2[4][8];
#pragma unroll
    for (int p = 0; p < 4; p++)
#pragma unroll
        for (int c = 0; c < 8; c++) acc2[p][c] = 0ULL;

    float4 aR[2], bR[2];
    aR[0] = *(const float4*)(A + (size_t)ar0 * EE + ak0 * 4);
    aR[1] = *(const float4*)(A + (size_t)ar1 * EE + ak1 * 4);
    bR[0] = *(const float4*)(W + (size_t)(nW0 + ar0) * EE + ak0 * 4);
    bR[1] = *(const float4*)(W + (size_t)(nW0 + ar1) * EE + ak1 * 4);
    {
        float* Ad = As0;  float* Bd = Bs0;
        Ad[(ak0 * 4 + 0) * 132 + ar0] = aR[0].x; Ad[(ak0 * 4 + 1) * 132 + ar0] = aR[0].y;
        Ad[(ak0 * 4 + 2) * 132 + ar0] = aR[0].z; Ad[(ak0 * 4 + 3) * 132 + ar0] = aR[0].w;
        Ad[(ak1 * 4 + 0) * 132 + ar1] = aR[1].x; Ad[(ak1 * 4 + 1) * 132 + ar1] = aR[1].y;
        Ad[(ak1 * 4 + 2) * 132 + ar1] = aR[1].z; Ad[(ak1 * 4 + 3) * 132 + ar1] = aR[1].w;
        Bd[(ak0 * 4 + 0) * 132 + ar0] = bR[0].x; Bd[(ak0 * 4 + 1) * 132 + ar0] = bR[0].y;
        Bd[(ak0 * 4 + 2) * 132 + ar0] = bR[0].z; Bd[(ak0 * 4 + 3) * 132 + ar0] = bR[0].w;
        Bd[(ak1 * 4 + 0) * 132 + ar1] = bR[1].x; Bd[(ak1 * 4 + 1) * 132 + ar1] = bR[1].y;
        Bd[(ak1 * 4 + 2) * 132 + ar1] = bR[1].z; Bd[(ak1 * 4 + 3) * 132 + ar1] = bR[1].w;
    }

    for (int it = 0; it < 32; ++it) {
        __syncthreads();
        if (it < 31) {
            int kn = (it + 1) * 16;
            aR[0] = *(const float4*)(A + (size_t)ar0 * EE + kn + ak0 * 4);
            aR[1] = *(const float4*)(A + (size_t)ar1 * EE + kn + ak1 * 4);
            bR[0] = *(const float4*)(W + (size_t)(nW0 + ar0) * EE + kn + ak0 * 4);
            bR[1] = *(const float4*)(W + (size_t)(nW0 + ar1) * EE + kn + ak1 * 4);
        }

        const float* Asc = As0 + (it & 1) * GTILE;
        const float* Bsc = Bs0 + (it & 1) * GTILE;
#pragma unroll
        for (int kk = 0; kk < 16; kk++) {
            ull apair[4];
            {
                ulonglong2 a0 = *(const ulonglong2*)&Asc[kk * 132 + r0];
                ulonglong2 a1 = *(const ulonglong2*)&Asc[kk * 132 + r0 + 4];
                apair[0] = a0.x; apair[1] = a0.y; apair[2] = a1.x; apair[3] = a1.y;
            }
            float4 bv0 = *(const float4*)&Bsc[kk * 132 + c0];
            float4 bv1 = *(const float4*)&Bsc[kk * 132 + c0 + 4];
            ull bd[8];
            DUP2(bd[0], bv0.x); DUP2(bd[1], bv0.y); DUP2(bd[2], bv0.z); DUP2(bd[3], bv0.w);
            DUP2(bd[4], bv1.x); DUP2(bd[5], bv1.y); DUP2(bd[6], bv1.z); DUP2(bd[7], bv1.w);
#pragma unroll
            for (int p = 0; p < 4; p++)
#pragma unroll
                for (int c = 0; c < 8; c++)
                    FMA2(acc2[p][c], apair[p], bd[c]);
        }

        if (it < 31) {
            float* Ad = As0 + ((it + 1) & 1) * GTILE;
            float* Bd = Bs0 + ((it + 1) & 1) * GTILE;
            Ad[(ak0 * 4 + 0) * 132 + ar0] = aR[0].x; Ad[(ak0 * 4 + 1) * 132 + ar0] = aR[0].y;
            Ad[(ak0 * 4 + 2) * 132 + ar0] = aR[0].z; Ad[(ak0 * 4 + 3) * 132 + ar0] = aR[0].w;
            Ad[(ak1 * 4 + 0) * 132 + ar1] = aR[1].x; Ad[(ak1 * 4 + 1) * 132 + ar1] = aR[1].y;
            Ad[(ak1 * 4 + 2) * 132 + ar1] = aR[1].z; Ad[(ak1 * 4 + 3) * 132 + ar1] = aR[1].w;
            Bd[(ak0 * 4 + 0) * 132 + ar0] = bR[0].x; Bd[(ak0 * 4 + 1) * 132 + ar0] = bR[0].y;
            Bd[(ak0 * 4 + 2) * 132 + ar0] = bR[0].z; Bd[(ak0 * 4 + 3) * 132 + ar0] = bR[0].w;
            Bd[(ak1 * 4 + 0) * 132 + ar1] = bR[1].x; Bd[(ak1 * 4 + 1) * 132 + ar1] = bR[1].y;
            Bd[(ak1 * 4 + 2) * 132 + ar1] = bR[1].z; Bd[(ak1 * 4 + 3) * 132 + ar1] = bR[1].w;
        }
    }

    float bs[8];
#pragma unroll
    for (int c = 0; c < 8; c++) {
        int n = n0 + c0 + c;
        bs[c] = dirb ? (bihb[n - 1024] + bhhb[n - 1024]) : (bihf[n] + bhhf[n]);
    }
#pragma unroll
    for (int p = 0; p < 4; p++) {
        float lo[8], hi[8];
#pragma unroll
        for (int c = 0; c < 8; c++) {
            UNPACK2(lo[c], hi[c], acc2[p][c]);
            lo[c] += bs[c]; hi[c] += bs[c];
        }
        size_t row_lo = (size_t)(bm * 128 + r0 + 2 * p) * NG + n0 + c0;
        size_t row_hi = row_lo + NG;
        *(float4*)(g_xg + row_lo)     = make_float4(lo[0], lo[1], lo[2], lo[3]);
        *(float4*)(g_xg + row_lo + 4) = make_float4(lo[4], lo[5], lo[6], lo[7]);
        *(float4*)(g_xg + row_hi)     = make_float4(hi[0], hi[1], hi[2], hi[3]);
        *(float4*)(g_xg + row_hi + 4) = make_float4(hi[4], hi[5], hi[6], hi[7]);
    }
}

// ---------------- kernel 3: persistent LSTM recurrence (R11 measured-best) --
// K-PACKED f32x2 accumulators. 128 blocks = 4 scans x 32 slices; 256 threads.
// Thread (ct = tid&7 unit, bt = tid>>3 0..31): 4 batches (bt + 32*bi), 4 gates.
// acc2[bi][g] = (even-k, odd-k) partial sums; zero DUP/PACK in inner loop.
// t=0 shortcut: h0 = 0 -> gates = xg only (no staging, no FMA loop, no zero_h).
#define WST 1028                     // sh_w unit stride: 4112B % 128B = 16 -> conflict-free
#define HST 260                      // sh_h batch stride: 1040B % 128B = 16 -> conflict-free

__global__ __launch_bounds__(256, 1) void lstm_kernel(const float* __restrict__ Whh_f,
                                                      const float* __restrict__ Whh_b) {
    extern __shared__ float sm[];
    float* sh_w = sm;                     // [8 units][1028] : g*256 + k (k contiguous)
    float* sh_h = sm + 8 * WST;           // [128 batches][260] : k contiguous

    const int tid = threadIdx.x;
    const int rec = blockIdx.x >> 5;      // (s1,f)(s1,b)(s2,f)(s2,b)
    const int slice = blockIdx.x & 31;
    const int s = rec >> 1;
    const int dir = rec & 1;
    const int ct = tid & 7;               // unit within slice
    const int bt = tid >> 3;              // 0..31
    const int j = slice * 8 + ct;         // hidden unit 0..255
    const float* Whh = dir ? Whh_b : Whh_f;
    const unsigned shh_u32 = (unsigned)__cvta_generic_to_shared(sh_h);
    unsigned* syncp = &g_syncs[rec * 32];
    unsigned* donep = &g_dones[rec * 32];

    // Build weights: sh_w[jj*WST + g*256 + k] = Whh[g*256 + slice*8 + jj][k]
    for (int idx = tid; idx < 8 * 4 * 64; idx += 256) {
        int jj = idx >> 8;                // 0..7
        int g  = (idx >> 6) & 3;
        int k4 = idx & 63;
        float4 v = *(const float4*)(Whh + (size_t)(g * 256 + slice * 8 + jj) * HH + k4 * 4);
        *(float4*)(sh_w + jj * WST + g * 256 + k4 * 4) = v;
    }

    const float* wbase = sh_w + ct * WST;
    float c_st[4] = {0.f, 0.f, 0.f, 0.f};

    for (int t = 0; t < 64; ++t) {
        const int l = dir ? (63 - t) : t;

        if (t > 0) {
            // stage h_prev via cp.async.cg in two chunks (k 0..127 / 128..255)
            const float* hsrc = g_h + (size_t)((t & 1) * 4 + rec) * BB * HH;
#pragma unroll 4
            for (int it = 0; it < 16; it++) {           // chunk0: k4 0..31
                int idx = tid + 256 * it;               // 4096 float4
                int b = idx >> 5, k4 = idx & 31;
                CP_ASYNC16(shh_u32 + (unsigned)(b * HST + k4 * 4) * 4u,
                           hsrc + (size_t)b * HH + k4 * 4);
            }
            CP_COMMIT();
#pragma unroll 4
            for (int it = 0; it < 16; it++) {           // chunk1: k4 32..63
                int idx = tid + 256 * it;
                int b = idx >> 5, k4 = 32 + (idx & 31);
                CP_ASYNC16(shh_u32 + (unsigned)(b * HST + k4 * 4) * 4u,
                           hsrc + (size_t)b * HH + k4 * 4);
            }
            CP_COMMIT();
        }

        // xg prefetch (independent LDGs, overlap with cp.async)
        const float* xgp = g_xg + ((size_t)(s * 8192 + l * 128)) * NG + dir * 1024 + j;
        float xv0[4], xv1[4], xv2[4], xv3[4];
#pragma unroll
        for (int g = 0; g < 4; g++) {
            xv0[g] = __ldcg(xgp + (size_t)bt * NG + g * 256);
            xv1[g] = __ldcg(xgp + (size_t)(bt + 32) * NG + g * 256);
            xv2[g] = __ldcg(xgp + (size_t)(bt + 64) * NG + g * 256);
            xv3[g] = __ldcg(xgp + (size_t)(bt + 96) * NG + g * 256);
        }

        // k-packed accumulators: acc2[bi][g] = (sum over even k, sum over odd k)
        ull acc2[4][4];
#pragma unroll
        for (int bi = 0; bi < 4; bi++)
#pragma unroll
            for (int g = 0; g < 4; g++) acc2[bi][g] = 0ULL;

        if (t > 0) {
            CP_WAIT(1);          // chunk0 landed
            __syncthreads();

            // first half (k4 0..31) while chunk1 streams
#pragma unroll 4
            for (int k4 = 0; k4 < 32; ++k4) {
                ulonglong2 hp[4], wp[4];
#pragma unroll
                for (int bi = 0; bi < 4; bi++)
                    hp[bi] = *(const ulonglong2*)(sh_h + (bt + 32 * bi) * HST + k4 * 4);
#pragma unroll
                for (int g = 0; g < 4; g++)
                    wp[g] = *(const ulonglong2*)(wbase + g * 256 + k4 * 4);
#pragma unroll
                for (int bi = 0; bi < 4; bi++)
#pragma unroll
                    for (int g = 0; g < 4; g++) {
                        FMA2(acc2[bi][g], hp[bi].x, wp[g].x);
                        FMA2(acc2[bi][g], hp[bi].y, wp[g].y);
                    }
            }

            CP_WAIT(0);          // chunk1 landed
            __syncthreads();

            // second half (k4 32..63)
#pragma unroll 4
            for (int k4 = 32; k4 < 64; ++k4) {
                ulonglong2 hp[4], wp[4];
#pragma unroll
                for (int bi = 0; bi < 4; bi++)
                    hp[bi] = *(const ulonglong2*)(sh_h + (bt + 32 * bi) * HST + k4 * 4);
#pragma unroll
                for (int g = 0; g < 4; g++)
                    wp[g] = *(const ulonglong2*)(wbase + g * 256 + k4 * 4);
#pragma unroll
                for (int bi = 0; bi < 4; bi++)
#pragma unroll
                    for (int g = 0; g < 4; g++) {
                        FMA2(acc2[bi][g], hp[bi].x, wp[g].x);
                        FMA2(acc2[bi][g], hp[bi].y, wp[g].y);
                    }
            }
        }

        // fold even/odd sums + xg, nonlinearity, state update, writes
        float* hdst = g_h + (size_t)(((t + 1) & 1) * 4 + rec) * BB * HH;
        float* odst = g_o + (size_t)s * LL * BB * DD + (size_t)l * BB * DD + dir * HH + j;
#pragma unroll
        for (int bi = 0; bi < 4; bi++) {
            int b = bt + 32 * bi;
            const float* xv = (bi == 0) ? xv0 : (bi == 1) ? xv1 : (bi == 2) ? xv2 : xv3;
            float gate[4];
#pragma unroll
            for (int g = 0; g < 4; g++) {
                float lo, hi;
                UNPACK2(lo, hi, acc2[bi][g]);
                gate[g] = xv[g] + lo + hi;
            }
            float ig = sig_fast(gate[0]);
            float fg = sig_fast(gate[1]);
            float gg = tanh_fast(gate[2]);
            float og = sig_fast(gate[3]);
            float c = fmaf(fg, c_st[bi], ig * gg);
            c_st[bi] = c;
            float h = og * tanh_fast(c);
            hdst[(size_t)b * HH + j] = h;
            odst[(size_t)b * DD] = h;
        }

        // per-scan barrier (32 blocks of this scan, all co-resident)
        __syncthreads();   // all threads' stores issued before arrival
        if (tid == 0) {
            __threadfence();
            atomicAdd(syncp, 1u);
            unsigned target = 32u * (unsigned)(t + 1);
            while (*((volatile unsigned*)syncp) < target) { }
            __threadfence();
        }
        __syncthreads();
    }

    // self-reset for graph replays (per scan)
    if (tid == 0) {
        unsigned old = atomicAdd(donep, 1u);
        if (old == 31u) {
            *donep = 0u;
            *syncp = 0u;
            __threadfence();
        }
    }
}

// ---------------- kernel 4: fused mp1 + attention + softmax + new_pool + sim
// One block per batch b, 256 threads. mp1 kept entirely in smem.
__global__ __launch_bounds__(256) void pool_kernel(float* __restrict__ out) {
    __shared__ float smp[DD];          // mp1 row
    __shared__ float spart[4][LL];
    __shared__ float sal[LL];          // softmax(att)
    __shared__ float red[256];
    int b = blockIdx.x, tid = threadIdx.x;
    int l = tid & 63, part = tid >> 6;

    // mp1[d] = max over time of o1[l][b][d]
    for (int d = tid; d < DD; d += 256) {
        float m = -FLT_MAX;
#pragma unroll 8
        for (int t = 0; t < LL; t++)
            m = fmaxf(m, g_o[(size_t)t * BB * DD + b * DD + d]);
        smp[d] = m;
    }
    __syncthreads();

    // att[l] = sum_d mp1[d] * o2_flat[b*DD*LL + d*LL + l]   (raw reshape)
    const float* o2 = g_o + (size_t)LL * BB * DD;
    {
        float a = 0.0f;
        const float* o2b = o2 + (size_t)b * DD * LL + l;
        for (int d = part * 128; d < part * 128 + 128; d++)
            a = fmaf(smp[d], o2b[(size_t)d * LL], a);
        spart[part][l] = a;
    }
    __syncthreads();
    if (tid < LL) {
        float at = spart[0][tid] + spart[1][tid] + spart[2][tid] + spart[3][tid];
        sal[tid] = at;
    }
    __syncthreads();
    if (tid < LL) {
        float mx = -FLT_MAX;
        for (int i = 0; i < LL; i++) mx = fmaxf(mx, sal[i]);
        float ssum = 0.0f;
        for (int i = 0; i < LL; i++) ssum += expf(sal[i] - mx);
        float mine = expf(sal[tid] - mx) / ssum;
        __syncwarp();
        sal[tid] = mine;
    }
    __syncthreads();

    // np[d] = sum_l sal[l] * o2_flat[b*LL*DD + l*DD + d]; sim = exp(-sum|mp1-np|)
    float local = 0.0f;
    for (int d = tid; d < DD; d += 256) {
        float np = 0.0f;
#pragma unroll 8
        for (int t = 0; t < LL; t++)
            np = fmaf(sal[t], o2[(size_t)b * LL * DD + t * DD + d], np);
        local += fabsf(smp[d] - np);
    }
    red[tid] = local;
    __syncthreads();
    for (int s2 = 128; s2 > 0; s2 >>= 1) {
        if (tid < s2) red[tid] += red[tid + s2];
        __syncthreads();
    }
    if (tid == 0) out[b] = expf(-red[0]);
}

// ---------------- kernel 5: commonWords + e1h/e2h ----------------
__global__ void e_kernel(const int* __restrict__ t1, const int* __restrict__ t2,
                         float* __restrict__ out) {
    __shared__ int s1[LL];
    __shared__ int spos[LL];
    __shared__ int smask[LL];
    __shared__ int shas;
    int b = blockIdx.x, tid = threadIdx.x;
    if (tid == 0) shas = 0;
    if (tid < LL) s1[tid] = t1[tid * BB + b];
    __syncthreads();
    if (tid < LL) {
        int tok2 = t2[tid * BB + b];
        int d = -1;
        for (int jj = 0; jj < LL; jj++)
            if (s1[jj] == tok2) d = jj;
        int m = (d > 1) && (tok2 > 0);
        smask[tid] = m;
        spos[tid] = min(max(d, 0), LL - 1);
        if (m) atomicOr(&shas, 1);
    }
    __syncthreads();
    int has = shas;
    const float* o1 = g_o;
    const float* o2 = g_o + (size_t)LL * BB * DD;
    for (int d = tid; d < DD; d += 256) {
        float m1 = -FLT_MAX, m2 = -FLT_MAX;
        for (int i = 0; i < LL; i++) {
            if (smask[i]) {
                m1 = fmaxf(m1, o1[(size_t)spos[i] * BB * DD + b * DD + d]);
                m2 = fmaxf(m2, o2[(size_t)i * BB * DD + b * DD + d]);
            }
        }
        out[128 + b * DD + d] = has ? m1 : 0.0f;
        out[128 + BB * DD + b * DD + d] = has ? m2 : 0.0f;
    }
}

// ---------------- launch ----------------
extern "C" void kernel_launch(void* const* d_in, const int* in_sizes, int n_in,
                              void* d_out, int out_size) {
    const int* t1 = (const int*)d_in[0];
    const int* t2 = (const int*)d_in[1];
    const float* emb = (const float*)d_in[2];
    const float* Wihf = (const float*)d_in[3];
    const float* Whhf = (const float*)d_in[4];
    const float* bihf = (const float*)d_in[5];
    const float* bhhf = (const float*)d_in[6];
    const float* Wihb = (const float*)d_in[7];
    const float* Whhb = (const float*)d_in[8];
    const float* bihb = (const float*)d_in[9];
    const float* bhhb = (const float*)d_in[10];
    float* out = (float*)d_out;

    gather_kernel<<<NROWS, 128>>>(t1, t2, emb);

    const int gemm_smem = 4 * GTILE * 4;   // 67,584 B
    cudaFuncSetAttribute(gemm_kernel, cudaFuncAttributeMaxDynamicSharedMemorySize, gemm_smem);
    dim3 ggrid(128, 16);
    gemm_kernel<<<ggrid, 256, gemm_smem>>>(Wihf, Wihb, bihf, bhhf, bihb, bhhb);

    const int lstm_smem = (8 * WST + 128 * HST) * 4;  // 166,016 B
    cudaFuncSetAttribute(lstm_kernel, cudaFuncAttributeMaxDynamicSharedMemorySize, lstm_smem);
    lstm_kernel<<<128, 256, lstm_smem>>>(Whhf, Whhb);

    pool_kernel<<<BB, 256>>>(out);
    e_kernel<<<BB, 256>>>(t1, t2, out);
}